// round 13
// baseline (speedup 1.0000x reference)
#include <cuda_runtime.h>
#include <cuda_fp16.h>
#include <stdint.h>
#include <math.h>

#define NT 365
#define NG 512
#define NX 256
#define HH 1024
#define KTOT 1280
#define G4 4096
#define NGHH (NG * HH)
#define NCHUNK 20                    // 4 chunks of xm (K=256) first, then 16 of h (K=1024)
#define STAGE_BYTES 32768            // A(16KB) + B(16KB)
#define NSTAGE 3
#define SMEM_ST_OFF (NSTAGE * STAGE_BYTES)
#define DSMEM_BYTES (SMEM_ST_OFF + 128 * 132 * 4)   // stages + dedicated sT = 162KB
#define NBLK 128

// ---------------- scratch (__device__ globals; no allocation) ----------------
__device__ __half g_h[2][NGHH];                     // ping-pong, fp16
__device__ __half g_Wp[(size_t)G4 * KTOT];          // rows permuted: r' = col*4 + gate
__device__ __half g_xm[(size_t)NT * NG * NX];       // fp16
__device__ float4 g_biasp[HH];                      // per col: (bi, bf, bg, bo)
__device__ volatile int g_flag[NBLK * 8];           // per-CTA progress flag, 32B apart

// ---------------- PTX helpers ----------------
static __device__ __forceinline__ uint32_t smem_u32(const void* p) {
    uint32_t a;
    asm("{ .reg .u64 t; cvta.to.shared.u64 t, %1; cvt.u32.u64 %0, t; }" : "=r"(a) : "l"(p));
    return a;
}
#define SWZ(o) ((o) ^ (((o) >> 3) & 0x70))

static __device__ __forceinline__ void cp16(uint32_t dst, const void* src) {
    asm volatile("cp.async.cg.shared.global [%0], [%1], 16;" :: "r"(dst), "l"(src));
}
static __device__ __forceinline__ void cp_commit() {
    asm volatile("cp.async.commit_group;" ::: "memory");
}
template <int N>
static __device__ __forceinline__ void cp_wait() {
    asm volatile("cp.async.wait_group %0;" :: "n"(N) : "memory");
}
static __device__ __forceinline__ void ldm4(uint32_t* r, uint32_t addr) {
    asm volatile("ldmatrix.sync.aligned.m8n8.x4.shared.b16 {%0,%1,%2,%3}, [%4];"
                 : "=r"(r[0]), "=r"(r[1]), "=r"(r[2]), "=r"(r[3]) : "r"(addr));
}
static __device__ __forceinline__ void mma_f16(float* d, const uint32_t* a,
                                               uint32_t b0, uint32_t b1) {
    asm volatile(
        "mma.sync.aligned.m16n8k16.row.col.f32.f16.f16.f32 "
        "{%0,%1,%2,%3}, {%4,%5,%6,%7}, {%8,%9}, {%0,%1,%2,%3};"
        : "+f"(d[0]), "+f"(d[1]), "+f"(d[2]), "+f"(d[3])
        : "r"(a[0]), "r"(a[1]), "r"(a[2]), "r"(a[3]), "r"(b0), "r"(b1));
}
static __device__ __forceinline__ float tanh_ap(float x) {
    float y;
    asm("tanh.approx.f32 %0, %1;" : "=f"(y) : "f"(x));
    return y;
}
static __device__ __forceinline__ float sig_ap(float x) {
    return fmaf(tanh_ap(0.5f * x), 0.5f, 0.5f);
}

// ---------------- prep kernels ----------------
__global__ void zero_kernel() {
    int i = blockIdx.x * 256 + threadIdx.x;
    if (i < NGHH) g_h[0][i] = __float2half(0.0f);
    if (i < NBLK * 8) g_flag[i] = 0;
}

__global__ void init_out_kernel(const float* __restrict__ b_lin, float* __restrict__ out) {
    int i = blockIdx.x * 256 + threadIdx.x;
    if (i < NT * NG) out[i] = b_lin[0];
}

__global__ void prep_bias_kernel(const float* __restrict__ b_ih, const float* __restrict__ b_hh) {
    int col = blockIdx.x * 256 + threadIdx.x;
    if (col >= HH) return;
    float4 v;
    v.x = b_ih[col] + b_hh[col];
    v.y = b_ih[HH + col] + b_hh[HH + col];
    v.z = b_ih[2 * HH + col] + b_hh[2 * HH + col];
    v.w = b_ih[3 * HH + col] + b_hh[3 * HH + col];
    g_biasp[col] = v;
}

// W' row r' = col*4 + gate; k cols 0..1023 from W_hh, 1024..1279 from W_ih (fused K)
__global__ void prep_W_kernel(const float* __restrict__ W_ih, const float* __restrict__ W_hh) {
    int k = blockIdx.x * 256 + threadIdx.x;
    int r = blockIdx.y;                       // old row: gate*1024 + col
    if (k >= KTOT) return;
    float v = (k < HH) ? W_hh[(size_t)r * HH + k]
                       : W_ih[(size_t)r * NX + (k - HH)];
    int gate = r >> 10, col = r & 1023;
    g_Wp[(size_t)(col * 4 + gate) * KTOT + k] = __float2half(v);
}

__global__ void prep_xm_kernel(const float* __restrict__ x, const float* __restrict__ maskX) {
    int idx = blockIdx.x * 256 + threadIdx.x;   // 0..NG*NX-1
    int t = blockIdx.y;
    size_t gi = (size_t)t * (NG * NX) + idx;
    g_xm[gi] = __float2half(x[gi] * maskX[idx]);
}

// ---------------- persistent fused LSTM: fine-grained producer flags ----------------
// grid 128 = 4 m-groups(128 batch) x 32 col-groups(32 hidden cols x 4 gates = 128 N)
// CTA (mgrp, cgrp): blockIdx.x = cgrp*4 + mgrp. h-chunk ih depends on producers
// (mgrp, 2*ih) and (mgrp, 2*ih+1) having finished step t-1 (flag >= t).
__global__ __launch_bounds__(256, 1) void lstm_persist_kernel(
    const float* __restrict__ W_lin, float* __restrict__ out) {
    extern __shared__ char dsm[];
    const uint32_t sbase = smem_u32(dsm);
    float* sT = (float*)(dsm + SMEM_ST_OFF);    // dedicated epilogue buffer
    const int tid = threadIdx.x;
    const int w = tid >> 5;
    const int lane = tid & 31;
    const int mgrp = blockIdx.x & 3;
    const int m0 = mgrp * 128;
    const int cgrp = blockIdx.x >> 2;
    const int n0g = cgrp * 128;

    const int prow = tid >> 3;                  // cp.async: 0..31 (+32*s)
    const int pseg = tid & 7;

    const int mw = (w & 3) * 32;                // warp m-offset
    const int nw = (w >> 2) * 64;               // warp n-offset
    const int lrow = lane & 15;
    const int lcol16 = (lane >> 4) * 16;

    const int tg = tid & 15;                    // epilogue col-pair group
    const int rr = tid >> 4;                    // epilogue row group (0..15)

    const int ecol = cgrp * 32 + tg * 2;
    const float4 bb0 = g_biasp[ecol];
    const float4 bb1 = g_biasp[ecol + 1];
    const float wl0 = W_lin[ecol];
    const float wl1 = W_lin[ecol + 1];

    float creg[8][2];                           // cell state, register-resident
#pragma unroll
    for (int p = 0; p < 8; ++p) { creg[p][0] = 0.0f; creg[p][1] = 0.0f; }

    // chunk order: i=0..3 -> xm (no h dependency), i=4..19 -> h(t-1)
    auto prefetch = [&](int tt, int i, int stage) {
        const uint32_t stb = sbase + stage * STAGE_BYTES;
        const __half* aSrc;
        int astr, ak, bk;
        if (i < 4) {
            aSrc = g_xm + (size_t)tt * NG * NX; astr = NX; ak = i * 64; bk = (16 + i) * 64;
        } else {
            aSrc = g_h[tt & 1]; astr = HH; ak = (i - 4) * 64; bk = (i - 4) * 64;
        }
#pragma unroll
        for (int s = 0; s < 4; ++s) {
            const int row = prow + s * 32;
            const uint32_t soff = SWZ(row * 128 + pseg * 16);
            cp16(stb + soff,         aSrc + (size_t)(m0 + row) * astr + ak + pseg * 8);
            cp16(stb + 16384 + soff, g_Wp + (size_t)(n0g + row) * KTOT + bk + pseg * 8);
        }
        cp_commit();
    };

    prefetch(0, 0, 0);
    prefetch(0, 1, 1);

#pragma unroll 1
    for (int t = 0; t < NT; ++t) {
        const int wbuf = (t + 1) & 1;

        float acc[2][8][4];
#pragma unroll
        for (int im = 0; im < 2; ++im)
#pragma unroll
            for (int jn = 0; jn < 8; ++jn)
#pragma unroll
                for (int r = 0; r < 4; ++r) acc[im][jn][r] = 0.0f;

        int stage = 0;
        for (int i = 0; i < NCHUNK; ++i) {
            if (i + 1 < NCHUNK) cp_wait<1>();   // chunk i landed (i+1 may be pending)
            else cp_wait<0>();
            __syncthreads();                     // data visible + compute(i-1) done
            if (i + 2 < NCHUNK) {
                const int j = i + 2;
                if (j >= 4) {
                    // wait for the 2 producers of this h-chunk's columns (step t-1 done)
                    const int g0 = (j - 4) * 2;
                    const volatile int* f0 = &g_flag[(g0 * 4 + mgrp) * 8];
                    const volatile int* f1 = &g_flag[((g0 + 1) * 4 + mgrp) * 8];
                    while (*f0 < t || *f1 < t) { }
                    __threadfence();            // acquire: order h reads after flag
                }
                int ns = stage + 2; if (ns >= NSTAGE) ns -= NSTAGE;
                prefetch(t, j, ns);
            }

            const uint32_t stb = sbase + stage * STAGE_BYTES;
#pragma unroll
            for (int ks = 0; ks < 4; ++ks) {     // K=16 per mma, 4 per 64-chunk
                const int kb = ks * 32;
                uint32_t ah[2][4], bh[4][4];
#pragma unroll
                for (int im = 0; im < 2; ++im)
                    ldm4(ah[im], stb + SWZ((mw + im * 16 + lrow) * 128 + kb + lcol16));
#pragma unroll
                for (int jb = 0; jb < 4; ++jb)
                    ldm4(bh[jb], stb + 16384 + SWZ((nw + jb * 16 + lrow) * 128 + kb + lcol16));
#pragma unroll
                for (int im = 0; im < 2; ++im)
#pragma unroll
                    for (int jn = 0; jn < 8; ++jn)
                        mma_f16(acc[im][jn], ah[im], bh[jn >> 1][jn & 1], bh[jn >> 1][(jn & 1) + 2]);
            }
            ++stage; if (stage >= NSTAGE) stage = 0;
        }

        __syncthreads();                        // all warps done reading stages

        // issue next step's x-chunk prefetches; land during epilogue
        if (t + 1 < NT) {
            prefetch(t + 1, 0, 0);
            prefetch(t + 1, 1, 1);
        }

        // ---- epilogue: fragments -> sT (transpose) -> cell update + fused out dot ----
#pragma unroll
        for (int im = 0; im < 2; ++im) {
            const int r0 = mw + im * 16 + (lane >> 2);
#pragma unroll
            for (int jn = 0; jn < 8; ++jn) {
                const int nb = nw + jn * 8 + (lane & 3) * 2;
                *(float2*)&sT[r0 * 132 + nb]       = make_float2(acc[im][jn][0], acc[im][jn][1]);
                *(float2*)&sT[(r0 + 8) * 132 + nb] = make_float2(acc[im][jn][2], acc[im][jn][3]);
            }
        }
        __syncthreads();

#pragma unroll
        for (int p = 0; p < 8; ++p) {
            const int row = p * 16 + rr;
            const int b = m0 + row;
            const float4 gA = *(float4*)&sT[row * 132 + tg * 8];
            const float4 gB = *(float4*)&sT[row * 132 + tg * 8 + 4];

            float i0 = sig_ap(gA.x + bb0.x);
            float f0 = sig_ap(gA.y + bb0.y);
            float q0 = tanh_ap(gA.z + bb0.z);
            float o0 = sig_ap(gA.w + bb0.w);
            float i1 = sig_ap(gB.x + bb1.x);
            float f1 = sig_ap(gB.y + bb1.y);
            float q1 = tanh_ap(gB.z + bb1.z);
            float o1 = sig_ap(gB.w + bb1.w);

            float cn0 = f0 * creg[p][0] + i0 * q0;
            float cn1 = f1 * creg[p][1] + i1 * q1;
            creg[p][0] = cn0;
            creg[p][1] = cn1;
            float h0 = o0 * tanh_ap(cn0);
            float h1 = o1 * tanh_ap(cn1);

            *(__half2*)&g_h[wbuf][(size_t)b * HH + ecol] = __floats2half2_rn(h0, h1);

            float v = h0 * wl0 + h1 * wl1;
#pragma unroll
            for (int o = 8; o; o >>= 1)
                v += __shfl_xor_sync(0xFFFFFFFFu, v, o);
            if (tg == 0) atomicAdd(&out[t * NG + b], v);
        }

        // release: publish h(t) for this CTA's 32 columns
        __syncthreads();                        // all h stores of this CTA issued
        if (tid == 0) {
            __threadfence();
            g_flag[blockIdx.x * 8] = t + 1;
        }
    }
}

// ---------------- host ----------------
extern "C" void kernel_launch(void* const* d_in, const int* in_sizes, int n_in,
                              void* d_out, int out_size) {
    const float* x     = (const float*)d_in[0];
    const float* maskX = (const float*)d_in[1];
    const float* W_ih  = (const float*)d_in[2];
    const float* W_hh  = (const float*)d_in[3];
    const float* b_ih  = (const float*)d_in[4];
    const float* b_hh  = (const float*)d_in[5];
    const float* W_lin = (const float*)d_in[6];
    const float* b_lin = (const float*)d_in[7];
    float* out = (float*)d_out;

    cudaFuncSetAttribute(lstm_persist_kernel,
                         cudaFuncAttributeMaxDynamicSharedMemorySize, DSMEM_BYTES);

    zero_kernel<<<(NGHH + 255) / 256, 256>>>();
    init_out_kernel<<<(NT * NG + 255) / 256, 256>>>(b_lin, out);
    prep_bias_kernel<<<(HH + 255) / 256, 256>>>(b_ih, b_hh);
    prep_W_kernel<<<dim3((KTOT + 255) / 256, G4), 256>>>(W_ih, W_hh);
    prep_xm_kernel<<<dim3((NG * NX) / 256, NT), 256>>>(x, maskX);

    lstm_persist_kernel<<<NBLK, 256, DSMEM_BYTES>>>(W_lin, out);
}

// round 14
// speedup vs baseline: 1.8614x; 1.8614x over previous
#include <cuda_runtime.h>
#include <cuda_fp16.h>
#include <stdint.h>
#include <math.h>

#define NT 365
#define NG 512
#define NX 256
#define HH 1024
#define KTOT 1280
#define G4 4096
#define NGHH (NG * HH)
#define NCHUNK 10                    // K=128 chunks: 0-1 = xm (K 256), 2-9 = h (K 1024)
#define STAGE_BYTES 65536            // A(32KB: 2 x 16KB subtiles) + B(32KB)
#define SMEM_ST_OFF (2 * STAGE_BYTES)
#define DSMEM_BYTES (SMEM_ST_OFF + 128 * 132 * 4)   // 2 stages + sT = 194KB
#define NBLK 128
#define GRPSZ 32                     // CTAs per m-group barrier

// ---------------- scratch (__device__ globals; no allocation) ----------------
__device__ __half g_h[2][NGHH];                     // ping-pong, fp16
__device__ __half g_Wp[(size_t)G4 * KTOT];          // rows permuted: r' = col*4 + gate
__device__ __half g_xm[(size_t)NT * NG * NX];       // fp16
__device__ float4 g_biasp[HH];                      // per col: (bi, bf, bg, bo)
__device__ unsigned int g_bar_cnt[4 * 32];          // per m-group, padded
__device__ volatile unsigned int g_bar_gen[4 * 32];

// ---------------- PTX helpers ----------------
static __device__ __forceinline__ uint32_t smem_u32(const void* p) {
    uint32_t a;
    asm("{ .reg .u64 t; cvta.to.shared.u64 t, %1; cvt.u32.u64 %0, t; }" : "=r"(a) : "l"(p));
    return a;
}
#define SWZ(o) ((o) ^ (((o) >> 3) & 0x70))

static __device__ __forceinline__ void cp16(uint32_t dst, const void* src) {
    asm volatile("cp.async.cg.shared.global [%0], [%1], 16;" :: "r"(dst), "l"(src));
}
static __device__ __forceinline__ void cp_commit() {
    asm volatile("cp.async.commit_group;" ::: "memory");
}
template <int N>
static __device__ __forceinline__ void cp_wait() {
    asm volatile("cp.async.wait_group %0;" :: "n"(N) : "memory");
}
static __device__ __forceinline__ void ldm4(uint32_t* r, uint32_t addr) {
    asm volatile("ldmatrix.sync.aligned.m8n8.x4.shared.b16 {%0,%1,%2,%3}, [%4];"
                 : "=r"(r[0]), "=r"(r[1]), "=r"(r[2]), "=r"(r[3]) : "r"(addr));
}
static __device__ __forceinline__ void mma_f16(float* d, const uint32_t* a,
                                               uint32_t b0, uint32_t b1) {
    asm volatile(
        "mma.sync.aligned.m16n8k16.row.col.f32.f16.f16.f32 "
        "{%0,%1,%2,%3}, {%4,%5,%6,%7}, {%8,%9}, {%0,%1,%2,%3};"
        : "+f"(d[0]), "+f"(d[1]), "+f"(d[2]), "+f"(d[3])
        : "r"(a[0]), "r"(a[1]), "r"(a[2]), "r"(a[3]), "r"(b0), "r"(b1));
}
static __device__ __forceinline__ float tanh_ap(float x) {
    float y;
    asm("tanh.approx.f32 %0, %1;" : "=f"(y) : "f"(x));
    return y;
}
static __device__ __forceinline__ float sig_ap(float x) {
    return fmaf(tanh_ap(0.5f * x), 0.5f, 0.5f);
}

// per-m-group split barrier (32 CTAs each; all CTAs co-resident)
static __device__ __forceinline__ void bar_arrive(int mgrp, int t) {
    __syncthreads();
    if (threadIdx.x == 0) {
        __threadfence();
        if (atomicAdd(&g_bar_cnt[mgrp * 32], 1u) == GRPSZ - 1) {
            g_bar_cnt[mgrp * 32] = 0;
            __threadfence();
            g_bar_gen[mgrp * 32] = (unsigned)(t + 1);
        }
    }
}
static __device__ __forceinline__ void bar_wait(int mgrp, int t) {
    if (threadIdx.x == 0) {
        while ((int)g_bar_gen[mgrp * 32] < t) { }
        __threadfence();
    }
    __syncthreads();
}

// ---------------- prep kernels ----------------
__global__ void zero_kernel() {
    int i = blockIdx.x * 256 + threadIdx.x;
    if (i < NGHH) g_h[0][i] = __float2half(0.0f);
    if (i < 4 * 32) { g_bar_cnt[i] = 0; g_bar_gen[i] = 0; }
}

__global__ void init_out_kernel(const float* __restrict__ b_lin, float* __restrict__ out) {
    int i = blockIdx.x * 256 + threadIdx.x;
    if (i < NT * NG) out[i] = b_lin[0];
}

__global__ void prep_bias_kernel(const float* __restrict__ b_ih, const float* __restrict__ b_hh) {
    int col = blockIdx.x * 256 + threadIdx.x;
    if (col >= HH) return;
    float4 v;
    v.x = b_ih[col] + b_hh[col];
    v.y = b_ih[HH + col] + b_hh[HH + col];
    v.z = b_ih[2 * HH + col] + b_hh[2 * HH + col];
    v.w = b_ih[3 * HH + col] + b_hh[3 * HH + col];
    g_biasp[col] = v;
}

// W' row r' = col*4 + gate; k cols 0..1023 from W_hh, 1024..1279 from W_ih (fused K)
__global__ void prep_W_kernel(const float* __restrict__ W_ih, const float* __restrict__ W_hh) {
    int k = blockIdx.x * 256 + threadIdx.x;
    int r = blockIdx.y;                       // old row: gate*1024 + col
    if (k >= KTOT) return;
    float v = (k < HH) ? W_hh[(size_t)r * HH + k]
                       : W_ih[(size_t)r * NX + (k - HH)];
    int gate = r >> 10, col = r & 1023;
    g_Wp[(size_t)(col * 4 + gate) * KTOT + k] = __float2half(v);
}

__global__ void prep_xm_kernel(const float* __restrict__ x, const float* __restrict__ maskX) {
    int idx = blockIdx.x * 256 + threadIdx.x;   // 0..NG*NX-1
    int t = blockIdx.y;
    size_t gi = (size_t)t * (NG * NX) + idx;
    g_xm[gi] = __float2half(x[gi] * maskX[idx]);
}

// ---------------- persistent fused LSTM: K=128 chunks, cross-step pipelined ----------------
// grid 128 = 4 m-groups(128 batch) x 32 col-groups(32 hidden cols x 4 gates = 128 N)
__global__ __launch_bounds__(256, 1) void lstm_persist_kernel(
    const float* __restrict__ W_lin, float* __restrict__ out) {
    extern __shared__ char dsm[];
    const uint32_t sbase = smem_u32(dsm);
    float* sT = (float*)(dsm + SMEM_ST_OFF);    // dedicated epilogue buffer
    const int tid = threadIdx.x;
    const int w = tid >> 5;
    const int lane = tid & 31;
    const int mgrp = blockIdx.x & 3;
    const int m0 = mgrp * 128;
    const int cgrp = blockIdx.x >> 2;
    const int n0g = cgrp * 128;

    const int prow = tid >> 3;                  // cp.async: 0..31 (+32*s)
    const int pseg = tid & 7;

    const int mw = (w & 3) * 32;                // warp m-offset
    const int nw = (w >> 2) * 64;               // warp n-offset
    const int lrow = lane & 15;
    const int lcol16 = (lane >> 4) * 16;

    const int tg = tid & 15;                    // epilogue col-pair group
    const int rr = tid >> 4;                    // epilogue row group (0..15)

    const int ecol = cgrp * 32 + tg * 2;
    const float4 bb0 = g_biasp[ecol];
    const float4 bb1 = g_biasp[ecol + 1];
    const float wl0 = W_lin[ecol];
    const float wl1 = W_lin[ecol + 1];

    const uint32_t st0 = sbase;
    const uint32_t st1 = sbase + STAGE_BYTES;

    float creg[8][2];                           // cell state, register-resident
#pragma unroll
    for (int p = 0; p < 8; ++p) { creg[p][0] = 0.0f; creg[p][1] = 0.0f; }

    float acc[2][8][4];                         // gate accumulators (carried across epilogue)

    // chunk i covers fused-K [i*128, i*128+128): i<2 -> xm, i>=2 -> h(t-1)
    auto prefetch = [&](int tt, int i, uint32_t stb) {
        const __half* aSrc;
        int astr, ak, bk;
        if (i < 2) {
            aSrc = g_xm + (size_t)tt * NG * NX; astr = NX; ak = i * 128; bk = 1024 + i * 128;
        } else {
            aSrc = g_h[tt & 1]; astr = HH; ak = (i - 2) * 128; bk = (i - 2) * 128;
        }
#pragma unroll
        for (int s2 = 0; s2 < 2; ++s2) {        // two 64-K subtiles
#pragma unroll
            for (int s = 0; s < 4; ++s) {
                const int row = prow + s * 32;
                const uint32_t soff = SWZ(row * 128 + pseg * 16);
                cp16(stb + s2 * 16384 + soff,
                     aSrc + (size_t)(m0 + row) * astr + ak + s2 * 64 + pseg * 8);
                cp16(stb + 32768 + s2 * 16384 + soff,
                     g_Wp + (size_t)(n0g + row) * KTOT + bk + s2 * 64 + pseg * 8);
            }
        }
        cp_commit();
    };

    auto compute = [&](uint32_t stb) {
#pragma unroll
        for (int s2 = 0; s2 < 2; ++s2) {
            const uint32_t ab = stb + s2 * 16384;
            const uint32_t bb = stb + 32768 + s2 * 16384;
#pragma unroll
            for (int ks = 0; ks < 4; ++ks) {
                const int kb = ks * 32;
                uint32_t ah[2][4], bh[4][4];
#pragma unroll
                for (int im = 0; im < 2; ++im)
                    ldm4(ah[im], ab + SWZ((mw + im * 16 + lrow) * 128 + kb + lcol16));
#pragma unroll
                for (int jb = 0; jb < 4; ++jb)
                    ldm4(bh[jb], bb + SWZ((nw + jb * 16 + lrow) * 128 + kb + lcol16));
#pragma unroll
                for (int im = 0; im < 2; ++im)
#pragma unroll
                    for (int jn = 0; jn < 8; ++jn)
                        mma_f16(acc[im][jn], ah[im], bh[jn >> 1][jn & 1], bh[jn >> 1][(jn & 1) + 2]);
            }
        }
    };

    // ---- prologue: chunk 0 of step 0 ----
    prefetch(0, 0, st0);
    cp_wait<0>();
    __syncthreads();
#pragma unroll
    for (int im = 0; im < 2; ++im)
#pragma unroll
        for (int jn = 0; jn < 8; ++jn)
#pragma unroll
            for (int r = 0; r < 4; ++r) acc[im][jn][r] = 0.0f;
    prefetch(0, 1, st1);
    compute(st0);

#pragma unroll 1
    for (int t = 0; t < NT; ++t) {
        const int wbuf = (t + 1) & 1;

        // ---- mainloop: chunks 1..9 (chunk 0 was computed in prior epilogue) ----
        for (int i = 1; i < NCHUNK; ++i) {
            cp_wait<0>();                       // chunk i landed
            __syncthreads();                    // visible + compute(i-1) done everywhere
            if (i + 1 < NCHUNK) {
                if (i == 1) bar_wait(mgrp, t);  // h(t-1) complete before first h prefetch
                prefetch(t, i + 1, (i + 1) & 1 ? st1 : st0);
            } else if (t + 1 < NT) {
                prefetch(t + 1, 0, st0);        // next step's x chunk (st0 free: ch8 done)
            }
            compute((i & 1) ? st1 : st0);
        }

        __syncthreads();                        // all warps done with last chunk's stage

        // ---- epilogue: sT stores, next-step chunk-0 MMA overlap, cell math ----
#pragma unroll
        for (int im = 0; im < 2; ++im) {
            const int r0 = mw + im * 16 + (lane >> 2);
#pragma unroll
            for (int jn = 0; jn < 8; ++jn) {
                const int nb = nw + jn * 8 + (lane & 3) * 2;
                *(float2*)&sT[r0 * 132 + nb]       = make_float2(acc[im][jn][0], acc[im][jn][1]);
                *(float2*)&sT[(r0 + 8) * 132 + nb] = make_float2(acc[im][jn][2], acc[im][jn][3]);
            }
        }
        cp_wait<0>();                           // next-step chunk 0 landed (if issued)
        __syncthreads();                        // sT visible + chunk-0 data visible

        if (t + 1 < NT) {
            // zero acc and issue chunk-0 HMMAs; they overlap the cell math below
#pragma unroll
            for (int im = 0; im < 2; ++im)
#pragma unroll
                for (int jn = 0; jn < 8; ++jn)
#pragma unroll
                    for (int r = 0; r < 4; ++r) acc[im][jn][r] = 0.0f;
            prefetch(t + 1, 1, st1);
            compute(st0);
        }

#pragma unroll
        for (int p = 0; p < 8; ++p) {
            const int row = p * 16 + rr;
            const int b = m0 + row;
            const float4 gA = *(float4*)&sT[row * 132 + tg * 8];
            const float4 gB = *(float4*)&sT[row * 132 + tg * 8 + 4];

            float i0 = sig_ap(gA.x + bb0.x);
            float f0 = sig_ap(gA.y + bb0.y);
            float q0 = tanh_ap(gA.z + bb0.z);
            float o0 = sig_ap(gA.w + bb0.w);
            float i1 = sig_ap(gB.x + bb1.x);
            float f1 = sig_ap(gB.y + bb1.y);
            float q1 = tanh_ap(gB.z + bb1.z);
            float o1 = sig_ap(gB.w + bb1.w);

            float cn0 = f0 * creg[p][0] + i0 * q0;
            float cn1 = f1 * creg[p][1] + i1 * q1;
            creg[p][0] = cn0;
            creg[p][1] = cn1;
            float h0 = o0 * tanh_ap(cn0);
            float h1 = o1 * tanh_ap(cn1);

            *(__half2*)&g_h[wbuf][(size_t)b * HH + ecol] = __floats2half2_rn(h0, h1);

            float v = h0 * wl0 + h1 * wl1;
#pragma unroll
            for (int o = 8; o; o >>= 1)
                v += __shfl_xor_sync(0xFFFFFFFFu, v, o);
            if (tg == 0) atomicAdd(&out[t * NG + b], v);
        }

        bar_arrive(mgrp, t);                    // release h(t) for this m-group
    }
}

// ---------------- host ----------------
extern "C" void kernel_launch(void* const* d_in, const int* in_sizes, int n_in,
                              void* d_out, int out_size) {
    const float* x     = (const float*)d_in[0];
    const float* maskX = (const float*)d_in[1];
    const float* W_ih  = (const float*)d_in[2];
    const float* W_hh  = (const float*)d_in[3];
    const float* b_ih  = (const float*)d_in[4];
    const float* b_hh  = (const float*)d_in[5];
    const float* W_lin = (const float*)d_in[6];
    const float* b_lin = (const float*)d_in[7];
    float* out = (float*)d_out;

    cudaFuncSetAttribute(lstm_persist_kernel,
                         cudaFuncAttributeMaxDynamicSharedMemorySize, DSMEM_BYTES);

    zero_kernel<<<(NGHH + 255) / 256, 256>>>();
    init_out_kernel<<<(NT * NG + 255) / 256, 256>>>(b_lin, out);
    prep_bias_kernel<<<(HH + 255) / 256, 256>>>(b_ih, b_hh);
    prep_W_kernel<<<dim3((KTOT + 255) / 256, G4), 256>>>(W_ih, W_hh);
    prep_xm_kernel<<<dim3((NG * NX) / 256, NT), 256>>>(x, maskX);

    lstm_persist_kernel<<<NBLK, 256, DSMEM_BYTES>>>(W_lin, out);
}

// round 15
// speedup vs baseline: 1.9302x; 1.0370x over previous
#include <cuda_runtime.h>
#include <cuda_fp16.h>
#include <stdint.h>
#include <math.h>

#define NT 365
#define NG 512
#define NX 256
#define HH 1024
#define KTOT 1280
#define G4 4096
#define NGHH (NG * HH)
#define NCHUNK 10                    // K=128 chunks: 0-1 = xm (K 256), 2-9 = h (K 1024)
#define STAGE_BYTES 65536            // A(32KB: 2 x 16KB subtiles) + B(32KB)
#define SMEM_ST_OFF (2 * STAGE_BYTES)
#define DSMEM_BYTES (SMEM_ST_OFF + 128 * 132 * 4)   // 2 stages + sT = 194KB
#define NBLK 128
#define GRPSZ 32                     // CTAs per m-group barrier

// ---------------- scratch (__device__ globals; no allocation) ----------------
__device__ __half g_h[2][NGHH];                     // ping-pong, fp16
__device__ __half g_Wp[(size_t)G4 * KTOT];          // rows permuted: r' = col*4 + gate
__device__ __half g_xm[(size_t)NT * NG * NX];       // fp16
__device__ float4 g_biasp[HH];                      // per col: (bi, bf, bg, bo)
__device__ unsigned int g_bar_cnt[4 * 32];          // per m-group, padded
__device__ volatile unsigned int g_bar_gen[4 * 32];

// ---------------- PTX helpers ----------------
static __device__ __forceinline__ uint32_t smem_u32(const void* p) {
    uint32_t a;
    asm("{ .reg .u64 t; cvta.to.shared.u64 t, %1; cvt.u32.u64 %0, t; }" : "=r"(a) : "l"(p));
    return a;
}
#define SWZ(o) ((o) ^ (((o) >> 3) & 0x70))

static __device__ __forceinline__ void cp16(uint32_t dst, const void* src) {
    asm volatile("cp.async.cg.shared.global [%0], [%1], 16;" :: "r"(dst), "l"(src));
}
static __device__ __forceinline__ void cp_commit() {
    asm volatile("cp.async.commit_group;" ::: "memory");
}
template <int N>
static __device__ __forceinline__ void cp_wait() {
    asm volatile("cp.async.wait_group %0;" :: "n"(N) : "memory");
}
static __device__ __forceinline__ void ldm4(uint32_t* r, uint32_t addr) {
    asm volatile("ldmatrix.sync.aligned.m8n8.x4.shared.b16 {%0,%1,%2,%3}, [%4];"
                 : "=r"(r[0]), "=r"(r[1]), "=r"(r[2]), "=r"(r[3]) : "r"(addr));
}
static __device__ __forceinline__ void mma_f16(float* d, const uint32_t* a,
                                               uint32_t b0, uint32_t b1) {
    asm volatile(
        "mma.sync.aligned.m16n8k16.row.col.f32.f16.f16.f32 "
        "{%0,%1,%2,%3}, {%4,%5,%6,%7}, {%8,%9}, {%0,%1,%2,%3};"
        : "+f"(d[0]), "+f"(d[1]), "+f"(d[2]), "+f"(d[3])
        : "r"(a[0]), "r"(a[1]), "r"(a[2]), "r"(a[3]), "r"(b0), "r"(b1));
}
static __device__ __forceinline__ float tanh_ap(float x) {
    float y;
    asm("tanh.approx.f32 %0, %1;" : "=f"(y) : "f"(x));
    return y;
}
static __device__ __forceinline__ float sig_ap(float x) {
    return fmaf(tanh_ap(0.5f * x), 0.5f, 0.5f);
}

// per-m-group split barrier (32 CTAs each; all CTAs co-resident)
static __device__ __forceinline__ void bar_arrive(int mgrp, int t) {
    __syncthreads();                         // whole CTA done with step t
    if (threadIdx.x == 0) {
        __threadfence();
        if (atomicAdd(&g_bar_cnt[mgrp * 32], 1u) == GRPSZ - 1) {
            g_bar_cnt[mgrp * 32] = 0;
            __threadfence();
            g_bar_gen[mgrp * 32] = (unsigned)(t + 1);
        }
    }
}
static __device__ __forceinline__ void bar_wait(int mgrp, int t) {
    if (threadIdx.x == 0) {
        while ((int)g_bar_gen[mgrp * 32] < t) { }
        __threadfence();
    }
    __syncthreads();
}

// ---------------- prep kernels ----------------
__global__ void zero_kernel() {
    int i = blockIdx.x * 256 + threadIdx.x;
    if (i < NGHH) g_h[0][i] = __float2half(0.0f);
    if (i < 4 * 32) { g_bar_cnt[i] = 0; g_bar_gen[i] = 0; }
}

__global__ void init_out_kernel(const float* __restrict__ b_lin, float* __restrict__ out) {
    int i = blockIdx.x * 256 + threadIdx.x;
    if (i < NT * NG) out[i] = b_lin[0];
}

__global__ void prep_bias_kernel(const float* __restrict__ b_ih, const float* __restrict__ b_hh) {
    int col = blockIdx.x * 256 + threadIdx.x;
    if (col >= HH) return;
    float4 v;
    v.x = b_ih[col] + b_hh[col];
    v.y = b_ih[HH + col] + b_hh[HH + col];
    v.z = b_ih[2 * HH + col] + b_hh[2 * HH + col];
    v.w = b_ih[3 * HH + col] + b_hh[3 * HH + col];
    g_biasp[col] = v;
}

// W' row r' = col*4 + gate; k cols 0..1023 from W_hh, 1024..1279 from W_ih (fused K)
__global__ void prep_W_kernel(const float* __restrict__ W_ih, const float* __restrict__ W_hh) {
    int k = blockIdx.x * 256 + threadIdx.x;
    int r = blockIdx.y;                       // old row: gate*1024 + col
    if (k >= KTOT) return;
    float v = (k < HH) ? W_hh[(size_t)r * HH + k]
                       : W_ih[(size_t)r * NX + (k - HH)];
    int gate = r >> 10, col = r & 1023;
    g_Wp[(size_t)(col * 4 + gate) * KTOT + k] = __float2half(v);
}

__global__ void prep_xm_kernel(const float* __restrict__ x, const float* __restrict__ maskX) {
    int idx = blockIdx.x * 256 + threadIdx.x;   // 0..NG*NX-1
    int t = blockIdx.y;
    size_t gi = (size_t)t * (NG * NX) + idx;
    g_xm[gi] = __float2half(x[gi] * maskX[idx]);
}

// ---------------- persistent fused LSTM: deep cross-step pipeline ----------------
// grid 128 = 4 m-groups(128 batch) x 32 col-groups(32 hidden cols x 4 gates = 128 N)
// Steady state: epilogue of step t computes chunks 0 and 1 of step t+1 (x-chunks),
// overlapping cell math and the inter-CTA barrier window; mainloop runs chunks 2..9.
__global__ __launch_bounds__(256, 1) void lstm_persist_kernel(
    const float* __restrict__ W_lin, float* __restrict__ out) {
    extern __shared__ char dsm[];
    const uint32_t sbase = smem_u32(dsm);
    float* sT = (float*)(dsm + SMEM_ST_OFF);    // dedicated epilogue buffer
    const int tid = threadIdx.x;
    const int w = tid >> 5;
    const int lane = tid & 31;
    const int mgrp = blockIdx.x & 3;
    const int m0 = mgrp * 128;
    const int cgrp = blockIdx.x >> 2;
    const int n0g = cgrp * 128;

    const int prow = tid >> 3;                  // cp.async: 0..31 (+32*s)
    const int pseg = tid & 7;

    const int mw = (w & 3) * 32;                // warp m-offset
    const int nw = (w >> 2) * 64;               // warp n-offset
    const int lrow = lane & 15;
    const int lcol16 = (lane >> 4) * 16;

    const int tg = tid & 15;                    // epilogue col-pair group
    const int rr = tid >> 4;                    // epilogue row group (0..15)

    const int ecol = cgrp * 32 + tg * 2;
    const float4 bb0 = g_biasp[ecol];
    const float4 bb1 = g_biasp[ecol + 1];
    const float wl0 = W_lin[ecol];
    const float wl1 = W_lin[ecol + 1];

    const uint32_t st0 = sbase;
    const uint32_t st1 = sbase + STAGE_BYTES;

    float creg[8][2];
#pragma unroll
    for (int p = 0; p < 8; ++p) { creg[p][0] = 0.0f; creg[p][1] = 0.0f; }

    float acc[2][8][4];

    // A-half (activation) of chunk i: i<2 -> xm, i>=2 -> h(t-1)
    auto prefetchA = [&](int tt, int i, uint32_t stb) {
        const __half* aSrc;
        int astr, ak;
        if (i < 2) { aSrc = g_xm + (size_t)tt * NG * NX; astr = NX; ak = i * 128; }
        else       { aSrc = g_h[tt & 1];                 astr = HH; ak = (i - 2) * 128; }
#pragma unroll
        for (int s2 = 0; s2 < 2; ++s2)
#pragma unroll
            for (int s = 0; s < 4; ++s) {
                const int row = prow + s * 32;
                const uint32_t soff = SWZ(row * 128 + pseg * 16);
                cp16(stb + s2 * 16384 + soff,
                     aSrc + (size_t)(m0 + row) * astr + ak + s2 * 64 + pseg * 8);
            }
        cp_commit();
    };
    // B-half (weights) of chunk i: never depends on h
    auto prefetchB = [&](int i, uint32_t stb) {
        const int bk = (i < 2) ? (1024 + i * 128) : ((i - 2) * 128);
#pragma unroll
        for (int s2 = 0; s2 < 2; ++s2)
#pragma unroll
            for (int s = 0; s < 4; ++s) {
                const int row = prow + s * 32;
                const uint32_t soff = SWZ(row * 128 + pseg * 16);
                cp16(stb + 32768 + s2 * 16384 + soff,
                     g_Wp + (size_t)(n0g + row) * KTOT + bk + s2 * 64 + pseg * 8);
            }
        cp_commit();
    };
    auto prefetch = [&](int tt, int i, uint32_t stb) {
        const __half* aSrc;
        int astr, ak, bk;
        if (i < 2) {
            aSrc = g_xm + (size_t)tt * NG * NX; astr = NX; ak = i * 128; bk = 1024 + i * 128;
        } else {
            aSrc = g_h[tt & 1]; astr = HH; ak = (i - 2) * 128; bk = (i - 2) * 128;
        }
#pragma unroll
        for (int s2 = 0; s2 < 2; ++s2)
#pragma unroll
            for (int s = 0; s < 4; ++s) {
                const int row = prow + s * 32;
                const uint32_t soff = SWZ(row * 128 + pseg * 16);
                cp16(stb + s2 * 16384 + soff,
                     aSrc + (size_t)(m0 + row) * astr + ak + s2 * 64 + pseg * 8);
                cp16(stb + 32768 + s2 * 16384 + soff,
                     g_Wp + (size_t)(n0g + row) * KTOT + bk + s2 * 64 + pseg * 8);
            }
        cp_commit();
    };

    // compute subtiles [s2b, s2e) of the K=128 chunk in stage stb
    auto compute = [&](uint32_t stb, int s2b, int s2e) {
        for (int s2 = s2b; s2 < s2e; ++s2) {
            const uint32_t ab = stb + s2 * 16384;
            const uint32_t bb = stb + 32768 + s2 * 16384;
#pragma unroll
            for (int ks = 0; ks < 4; ++ks) {
                const int kb = ks * 32;
                uint32_t ah[2][4], bh[4][4];
#pragma unroll
                for (int im = 0; im < 2; ++im)
                    ldm4(ah[im], ab + SWZ((mw + im * 16 + lrow) * 128 + kb + lcol16));
#pragma unroll
                for (int jb = 0; jb < 4; ++jb)
                    ldm4(bh[jb], bb + SWZ((nw + jb * 16 + lrow) * 128 + kb + lcol16));
#pragma unroll
                for (int im = 0; im < 2; ++im)
#pragma unroll
                    for (int jn = 0; jn < 8; ++jn)
                        mma_f16(acc[im][jn], ah[im], bh[jn >> 1][jn & 1], bh[jn >> 1][(jn & 1) + 2]);
            }
        }
    };

    // ---- prologue: chunks 0,1 of step 0; prefetch chunk 2 (h(-1) = zeros) ----
    prefetch(0, 0, st0);
    cp_wait<0>(); __syncthreads();
#pragma unroll
    for (int im = 0; im < 2; ++im)
#pragma unroll
        for (int jn = 0; jn < 8; ++jn)
#pragma unroll
            for (int r = 0; r < 4; ++r) acc[im][jn][r] = 0.0f;
    prefetch(0, 1, st1);
    compute(st0, 0, 2);                         // chunk 0
    __syncthreads();                            // all warps done with st0
    prefetch(0, 2, st0);                        // chunk 2 (h is pre-zeroed)
    cp_wait<1>(); __syncthreads();              // chunk 1 landed
    compute(st1, 0, 2);                         // chunk 1

#pragma unroll 1
    for (int t = 0; t < NT; ++t) {
        const int wbuf = (t + 1) & 1;

        // ---- mainloop: chunks 2..9 (0,1 computed in prior epilogue/prologue) ----
        for (int i = 2; i < NCHUNK; ++i) {
            cp_wait<0>();                       // chunk i landed
            __syncthreads();                    // visible + compute(i-1) done everywhere
            if (i + 1 < NCHUNK) prefetch(t, i + 1, ((i + 1) & 1) ? st1 : st0);
            else if (t + 1 < NT) prefetch(t + 1, 0, st0);   // next step's chunk 0
            compute((i & 1) ? st1 : st0, 0, 2);
        }

        __syncthreads();                        // all warps done with last chunk's stage

        // ---- epilogue ----
#pragma unroll
        for (int im = 0; im < 2; ++im) {
            const int r0 = mw + im * 16 + (lane >> 2);
#pragma unroll
            for (int jn = 0; jn < 8; ++jn) {
                const int nb = nw + jn * 8 + (lane & 3) * 2;
                *(float2*)&sT[r0 * 132 + nb]       = make_float2(acc[im][jn][0], acc[im][jn][1]);
                *(float2*)&sT[(r0 + 8) * 132 + nb] = make_float2(acc[im][jn][2], acc[im][jn][3]);
            }
        }
        cp_wait<0>();                           // next-step chunk 0 landed (if issued)
        __syncthreads();                        // sT + chunk-0 data visible

        if (t + 1 < NT) {
            // zero acc, start chunk-1 fetch, compute chunk 0 (overlaps cell math below)
#pragma unroll
            for (int im = 0; im < 2; ++im)
#pragma unroll
                for (int jn = 0; jn < 8; ++jn)
#pragma unroll
                    for (int r = 0; r < 4; ++r) acc[im][jn][r] = 0.0f;
            prefetch(t + 1, 1, st1);
            compute(st0, 0, 2);                 // chunk 0 of t+1
        }

        // cell update + fused output dot (fma/MUFU pipes; overlaps chunk-0 HMMAs)
#pragma unroll
        for (int p = 0; p < 8; ++p) {
            const int row = p * 16 + rr;
            const int b = m0 + row;
            const float4 gA = *(float4*)&sT[row * 132 + tg * 8];
            const float4 gB = *(float4*)&sT[row * 132 + tg * 8 + 4];

            float i0 = sig_ap(gA.x + bb0.x);
            float f0 = sig_ap(gA.y + bb0.y);
            float q0 = tanh_ap(gA.z + bb0.z);
            float o0 = sig_ap(gA.w + bb0.w);
            float i1 = sig_ap(gB.x + bb1.x);
            float f1 = sig_ap(gB.y + bb1.y);
            float q1 = tanh_ap(gB.z + bb1.z);
            float o1 = sig_ap(gB.w + bb1.w);

            float cn0 = f0 * creg[p][0] + i0 * q0;
            float cn1 = f1 * creg[p][1] + i1 * q1;
            creg[p][0] = cn0;
            creg[p][1] = cn1;
            float h0 = o0 * tanh_ap(cn0);
            float h1 = o1 * tanh_ap(cn1);

            *(__half2*)&g_h[wbuf][(size_t)b * HH + ecol] = __floats2half2_rn(h0, h1);

            float v = h0 * wl0 + h1 * wl1;
#pragma unroll
            for (int o = 8; o; o >>= 1)
                v += __shfl_xor_sync(0xFFFFFFFFu, v, o);
            if (tg == 0) atomicAdd(&out[t * NG + b], v);
        }

        bar_arrive(mgrp, t);                    // has __syncthreads: st0 fully consumed

        if (t + 1 < NT) {
            prefetchB(2, st0);                  // chunk-2 weights: no h dependency
            cp_wait<1>(); __syncthreads();      // chunk 1 landed (B2 may be in flight)
            compute(st1, 0, 1);                 // chunk-1 subtile 0: hides barrier skew
            bar_wait(mgrp, t + 1);              // h(t) fully published group-wide
            prefetchA(t + 1, 2, st0);           // chunk-2 h data
            compute(st1, 1, 2);                 // chunk-1 subtile 1: hides A fetch
        }
    }
}

// ---------------- host ----------------
extern "C" void kernel_launch(void* const* d_in, const int* in_sizes, int n_in,
                              void* d_out, int out_size) {
    const float* x     = (const float*)d_in[0];
    const float* maskX = (const float*)d_in[1];
    const float* W_ih  = (const float*)d_in[2];
    const float* W_hh  = (const float*)d_in[3];
    const float* b_ih  = (const float*)d_in[4];
    const float* b_hh  = (const float*)d_in[5];
    const float* W_lin = (const float*)d_in[6];
    const float* b_lin = (const float*)d_in[7];
    float* out = (float*)d_out;

    cudaFuncSetAttribute(lstm_persist_kernel,
                         cudaFuncAttributeMaxDynamicSharedMemorySize, DSMEM_BYTES);

    zero_kernel<<<(NGHH + 255) / 256, 256>>>();
    init_out_kernel<<<(NT * NG + 255) / 256, 256>>>(b_lin, out);
    prep_bias_kernel<<<(HH + 255) / 256, 256>>>(b_ih, b_hh);
    prep_W_kernel<<<dim3((KTOT + 255) / 256, G4), 256>>>(W_ih, W_hh);
    prep_xm_kernel<<<dim3((NG * NX) / 256, NT), 256>>>(x, maskX);

    lstm_persist_kernel<<<NBLK, 256, DSMEM_BYTES>>>(W_lin, out);
}

// round 16
// speedup vs baseline: 1.9341x; 1.0020x over previous
#include <cuda_runtime.h>
#include <cuda_fp16.h>
#include <stdint.h>
#include <math.h>

#define NT 365
#define NG 512
#define NX 256
#define HH 1024
#define KTOT 1280
#define G4 4096
#define NGHH (NG * HH)
#define NCHUNK 10                    // K=128 chunks: 0-1 = xm (K 256), 2-9 = h (K 1024)
#define STAGE_BYTES 65536            // A(32KB: 2 x 16KB subtiles) + B(32KB)
#define SMEM_ST_OFF (2 * STAGE_BYTES)
#define DSMEM_BYTES (SMEM_ST_OFF + 128 * 132 * 4)   // 2 stages + sT = 194KB
#define NBLK 128
#define GRPSZ 32                     // CTAs per m-group barrier

// ---------------- scratch (__device__ globals; no allocation) ----------------
__device__ __half g_h[2][NGHH];                     // ping-pong, fp16
__device__ __half g_Wp[(size_t)G4 * KTOT];          // rows permuted: r' = col*4 + gate
__device__ __half g_xm[(size_t)NT * NG * NX];       // fp16
__device__ float4 g_biasp[HH];                      // per col: (bi, bf, bg, bo)
__device__ unsigned int g_bar_cnt[4 * 32];          // per m-group, padded
__device__ volatile unsigned int g_bar_gen[4 * 32];

// ---------------- PTX helpers ----------------
static __device__ __forceinline__ uint32_t smem_u32(const void* p) {
    uint32_t a;
    asm("{ .reg .u64 t; cvta.to.shared.u64 t, %1; cvt.u32.u64 %0, t; }" : "=r"(a) : "l"(p));
    return a;
}
#define SWZ(o) ((o) ^ (((o) >> 3) & 0x70))

static __device__ __forceinline__ void cp16(uint32_t dst, const void* src) {
    asm volatile("cp.async.cg.shared.global [%0], [%1], 16;" :: "r"(dst), "l"(src));
}
static __device__ __forceinline__ void cp_commit() {
    asm volatile("cp.async.commit_group;" ::: "memory");
}
template <int N>
static __device__ __forceinline__ void cp_wait() {
    asm volatile("cp.async.wait_group %0;" :: "n"(N) : "memory");
}
static __device__ __forceinline__ void ldm4(uint32_t* r, uint32_t addr) {
    asm volatile("ldmatrix.sync.aligned.m8n8.x4.shared.b16 {%0,%1,%2,%3}, [%4];"
                 : "=r"(r[0]), "=r"(r[1]), "=r"(r[2]), "=r"(r[3]) : "r"(addr));
}
static __device__ __forceinline__ void mma_f16(float* d, const uint32_t* a,
                                               uint32_t b0, uint32_t b1) {
    asm volatile(
        "mma.sync.aligned.m16n8k16.row.col.f32.f16.f16.f32 "
        "{%0,%1,%2,%3}, {%4,%5,%6,%7}, {%8,%9}, {%0,%1,%2,%3};"
        : "+f"(d[0]), "+f"(d[1]), "+f"(d[2]), "+f"(d[3])
        : "r"(a[0]), "r"(a[1]), "r"(a[2]), "r"(a[3]), "r"(b0), "r"(b1));
}
static __device__ __forceinline__ float tanh_ap(float x) {
    float y;
    asm("tanh.approx.f32 %0, %1;" : "=f"(y) : "f"(x));
    return y;
}
static __device__ __forceinline__ float sig_ap(float x) {
    return fmaf(tanh_ap(0.5f * x), 0.5f, 0.5f);
}

// per-m-group split barrier (32 CTAs each; all CTAs co-resident)
static __device__ __forceinline__ void bar_arrive(int mgrp, int t) {
    __syncthreads();                         // whole CTA done with step t
    if (threadIdx.x == 0) {
        __threadfence();
        if (atomicAdd(&g_bar_cnt[mgrp * 32], 1u) == GRPSZ - 1) {
            g_bar_cnt[mgrp * 32] = 0;
            __threadfence();
            g_bar_gen[mgrp * 32] = (unsigned)(t + 1);
        }
    }
}
static __device__ __forceinline__ void bar_wait(int mgrp, int t) {
    if (threadIdx.x == 0) {
        while ((int)g_bar_gen[mgrp * 32] < t) { }
        __threadfence();
    }
    __syncthreads();
}

// ---------------- prep kernels ----------------
__global__ void zero_kernel() {
    int i = blockIdx.x * 256 + threadIdx.x;
    if (i < NGHH) g_h[0][i] = __float2half(0.0f);
    if (i < 4 * 32) { g_bar_cnt[i] = 0; g_bar_gen[i] = 0; }
}

__global__ void init_out_kernel(const float* __restrict__ b_lin, float* __restrict__ out) {
    int i = blockIdx.x * 256 + threadIdx.x;
    if (i < NT * NG) out[i] = b_lin[0];
}

__global__ void prep_bias_kernel(const float* __restrict__ b_ih, const float* __restrict__ b_hh) {
    int col = blockIdx.x * 256 + threadIdx.x;
    if (col >= HH) return;
    float4 v;
    v.x = b_ih[col] + b_hh[col];
    v.y = b_ih[HH + col] + b_hh[HH + col];
    v.z = b_ih[2 * HH + col] + b_hh[2 * HH + col];
    v.w = b_ih[3 * HH + col] + b_hh[3 * HH + col];
    g_biasp[col] = v;
}

// W' row r' = col*4 + gate; k cols 0..1023 from W_hh, 1024..1279 from W_ih (fused K)
__global__ void prep_W_kernel(const float* __restrict__ W_ih, const float* __restrict__ W_hh) {
    int k = blockIdx.x * 256 + threadIdx.x;
    int r = blockIdx.y;                       // old row: gate*1024 + col
    if (k >= KTOT) return;
    float v = (k < HH) ? W_hh[(size_t)r * HH + k]
                       : W_ih[(size_t)r * NX + (k - HH)];
    int gate = r >> 10, col = r & 1023;
    g_Wp[(size_t)(col * 4 + gate) * KTOT + k] = __float2half(v);
}

__global__ void prep_xm_kernel(const float* __restrict__ x, const float* __restrict__ maskX) {
    int idx = blockIdx.x * 256 + threadIdx.x;   // 0..NG*NX-1
    int t = blockIdx.y;
    size_t gi = (size_t)t * (NG * NX) + idx;
    g_xm[gi] = __float2half(x[gi] * maskX[idx]);
}

// ---------------- persistent fused LSTM: deep cross-step pipeline ----------------
// grid 128 = 4 m-groups(128 batch) x 32 col-groups(32 hidden cols x 4 gates = 128 N)
// Steady state: epilogue of step t computes chunks 0 and 1 of step t+1 (x-chunks),
// interleaved with the cell math and the inter-CTA barrier window.
__global__ __launch_bounds__(256, 1) void lstm_persist_kernel(
    const float* __restrict__ W_lin, float* __restrict__ out) {
    extern __shared__ char dsm[];
    const uint32_t sbase = smem_u32(dsm);
    float* sT = (float*)(dsm + SMEM_ST_OFF);    // dedicated epilogue buffer
    const int tid = threadIdx.x;
    const int w = tid >> 5;
    const int lane = tid & 31;
    const int mgrp = blockIdx.x & 3;
    const int m0 = mgrp * 128;
    const int cgrp = blockIdx.x >> 2;
    const int n0g = cgrp * 128;

    const int prow = tid >> 3;                  // cp.async: 0..31 (+32*s)
    const int pseg = tid & 7;

    const int mw = (w & 3) * 32;                // warp m-offset
    const int nw = (w >> 2) * 64;               // warp n-offset
    const int lrow = lane & 15;
    const int lcol16 = (lane >> 4) * 16;

    const int tg = tid & 15;                    // epilogue col-pair group
    const int rr = tid >> 4;                    // epilogue row group (0..15)

    const int ecol = cgrp * 32 + tg * 2;
    const float4 bb0 = g_biasp[ecol];
    const float4 bb1 = g_biasp[ecol + 1];
    const float wl0 = W_lin[ecol];
    const float wl1 = W_lin[ecol + 1];

    const uint32_t st0 = sbase;
    const uint32_t st1 = sbase + STAGE_BYTES;

    float creg[8][2];
#pragma unroll
    for (int p = 0; p < 8; ++p) { creg[p][0] = 0.0f; creg[p][1] = 0.0f; }

    float acc[2][8][4];

    // A-half (activation) of chunk i: i<2 -> xm, i>=2 -> h(t-1)
    auto prefetchA = [&](int tt, int i, uint32_t stb) {
        const __half* aSrc;
        int astr, ak;
        if (i < 2) { aSrc = g_xm + (size_t)tt * NG * NX; astr = NX; ak = i * 128; }
        else       { aSrc = g_h[tt & 1];                 astr = HH; ak = (i - 2) * 128; }
#pragma unroll
        for (int s2 = 0; s2 < 2; ++s2)
#pragma unroll
            for (int s = 0; s < 4; ++s) {
                const int row = prow + s * 32;
                const uint32_t soff = SWZ(row * 128 + pseg * 16);
                cp16(stb + s2 * 16384 + soff,
                     aSrc + (size_t)(m0 + row) * astr + ak + s2 * 64 + pseg * 8);
            }
        cp_commit();
    };
    // B-half (weights) of chunk i: never depends on h
    auto prefetchB = [&](int i, uint32_t stb) {
        const int bk = (i < 2) ? (1024 + i * 128) : ((i - 2) * 128);
#pragma unroll
        for (int s2 = 0; s2 < 2; ++s2)
#pragma unroll
            for (int s = 0; s < 4; ++s) {
                const int row = prow + s * 32;
                const uint32_t soff = SWZ(row * 128 + pseg * 16);
                cp16(stb + 32768 + s2 * 16384 + soff,
                     g_Wp + (size_t)(n0g + row) * KTOT + bk + s2 * 64 + pseg * 8);
            }
        cp_commit();
    };
    auto prefetch = [&](int tt, int i, uint32_t stb) {
        const __half* aSrc;
        int astr, ak, bk;
        if (i < 2) {
            aSrc = g_xm + (size_t)tt * NG * NX; astr = NX; ak = i * 128; bk = 1024 + i * 128;
        } else {
            aSrc = g_h[tt & 1]; astr = HH; ak = (i - 2) * 128; bk = (i - 2) * 128;
        }
#pragma unroll
        for (int s2 = 0; s2 < 2; ++s2)
#pragma unroll
            for (int s = 0; s < 4; ++s) {
                const int row = prow + s * 32;
                const uint32_t soff = SWZ(row * 128 + pseg * 16);
                cp16(stb + s2 * 16384 + soff,
                     aSrc + (size_t)(m0 + row) * astr + ak + s2 * 64 + pseg * 8);
                cp16(stb + 32768 + s2 * 16384 + soff,
                     g_Wp + (size_t)(n0g + row) * KTOT + bk + s2 * 64 + pseg * 8);
            }
        cp_commit();
    };

    // compute subtiles [s2b, s2e) of the K=128 chunk in stage stb
    auto compute = [&](uint32_t stb, int s2b, int s2e) {
        for (int s2 = s2b; s2 < s2e; ++s2) {
            const uint32_t ab = stb + s2 * 16384;
            const uint32_t bb = stb + 32768 + s2 * 16384;
#pragma unroll
            for (int ks = 0; ks < 4; ++ks) {
                const int kb = ks * 32;
                uint32_t ah[2][4], bh[4][4];
#pragma unroll
                for (int im = 0; im < 2; ++im)
                    ldm4(ah[im], ab + SWZ((mw + im * 16 + lrow) * 128 + kb + lcol16));
#pragma unroll
                for (int jb = 0; jb < 4; ++jb)
                    ldm4(bh[jb], bb + SWZ((nw + jb * 16 + lrow) * 128 + kb + lcol16));
#pragma unroll
                for (int im = 0; im < 2; ++im)
#pragma unroll
                    for (int jn = 0; jn < 8; ++jn)
                        mma_f16(acc[im][jn], ah[im], bh[jn >> 1][jn & 1], bh[jn >> 1][(jn & 1) + 2]);
            }
        }
    };

    // cell update + fused output dot for epilogue points [p0, p1)
    auto cell = [&](int p0, int p1, int t, int wbuf) {
        for (int p = p0; p < p1; ++p) {
            const int row = p * 16 + rr;
            const int b = m0 + row;
            const float4 gA = *(float4*)&sT[row * 132 + tg * 8];
            const float4 gB = *(float4*)&sT[row * 132 + tg * 8 + 4];

            float i0 = sig_ap(gA.x + bb0.x);
            float f0 = sig_ap(gA.y + bb0.y);
            float q0 = tanh_ap(gA.z + bb0.z);
            float o0 = sig_ap(gA.w + bb0.w);
            float i1 = sig_ap(gB.x + bb1.x);
            float f1 = sig_ap(gB.y + bb1.y);
            float q1 = tanh_ap(gB.z + bb1.z);
            float o1 = sig_ap(gB.w + bb1.w);

            float cn0 = f0 * creg[p][0] + i0 * q0;
            float cn1 = f1 * creg[p][1] + i1 * q1;
            creg[p][0] = cn0;
            creg[p][1] = cn1;
            float h0 = o0 * tanh_ap(cn0);
            float h1 = o1 * tanh_ap(cn1);

            *(__half2*)&g_h[wbuf][(size_t)b * HH + ecol] = __floats2half2_rn(h0, h1);

            float v = h0 * wl0 + h1 * wl1;
#pragma unroll
            for (int o = 8; o; o >>= 1)
                v += __shfl_xor_sync(0xFFFFFFFFu, v, o);
            if (tg == 0) atomicAdd(&out[t * NG + b], v);
        }
    };

    // ---- prologue: chunks 0,1 of step 0; prefetch chunk 2 (h(-1) = zeros) ----
    prefetch(0, 0, st0);
    cp_wait<0>(); __syncthreads();
#pragma unroll
    for (int im = 0; im < 2; ++im)
#pragma unroll
        for (int jn = 0; jn < 8; ++jn)
#pragma unroll
            for (int r = 0; r < 4; ++r) acc[im][jn][r] = 0.0f;
    prefetch(0, 1, st1);
    compute(st0, 0, 2);                         // chunk 0
    __syncthreads();                            // all warps done with st0
    prefetch(0, 2, st0);                        // chunk 2 (h is pre-zeroed)
    cp_wait<1>(); __syncthreads();              // chunk 1 landed
    compute(st1, 0, 2);                         // chunk 1

#pragma unroll 1
    for (int t = 0; t < NT; ++t) {
        const int wbuf = (t + 1) & 1;

        // ---- mainloop: chunks 2..9 (0,1 computed in prior epilogue/prologue) ----
        for (int i = 2; i < NCHUNK; ++i) {
            cp_wait<0>();                       // chunk i landed
            __syncthreads();                    // visible + compute(i-1) done everywhere
            if (i + 1 < NCHUNK) prefetch(t, i + 1, ((i + 1) & 1) ? st1 : st0);
            else if (t + 1 < NT) prefetch(t + 1, 0, st0);   // next step's chunk 0
            compute((i & 1) ? st1 : st0, 0, 2);
        }

        __syncthreads();                        // all warps done with last chunk's stage

        // ---- epilogue ----
#pragma unroll
        for (int im = 0; im < 2; ++im) {
            const int r0 = mw + im * 16 + (lane >> 2);
#pragma unroll
            for (int jn = 0; jn < 8; ++jn) {
                const int nb = nw + jn * 8 + (lane & 3) * 2;
                *(float2*)&sT[r0 * 132 + nb]       = make_float2(acc[im][jn][0], acc[im][jn][1]);
                *(float2*)&sT[(r0 + 8) * 132 + nb] = make_float2(acc[im][jn][2], acc[im][jn][3]);
            }
        }
        cp_wait<0>();                           // next-step chunk 0 landed (if issued)
        __syncthreads();                        // sT + chunk-0 data visible

        if (t + 1 < NT) {
            // zero acc, start chunk-1 fetch; interleave chunk-0 HMMA issue with
            // the MUFU-heavy cell math (disjoint pipes, per-warp issue alternates)
#pragma unroll
            for (int im = 0; im < 2; ++im)
#pragma unroll
                for (int jn = 0; jn < 8; ++jn)
#pragma unroll
                    for (int r = 0; r < 4; ++r) acc[im][jn][r] = 0.0f;
            prefetch(t + 1, 1, st1);
            compute(st0, 0, 1);                 // chunk-0 subtile 0 (issue backpressure)
            cell(0, 4, t, wbuf);                // cell half 1 overlaps tensor drain
            compute(st0, 1, 2);                 // chunk-0 subtile 1
            cell(4, 8, t, wbuf);                // cell half 2 overlaps tensor drain
        } else {
            cell(0, 8, t, wbuf);
        }

        bar_arrive(mgrp, t);                    // has __syncthreads: st0 fully consumed

        if (t + 1 < NT) {
            prefetchB(2, st0);                  // chunk-2 weights: no h dependency
            cp_wait<1>(); __syncthreads();      // chunk 1 landed (B2 may be in flight)
            compute(st1, 0, 1);                 // chunk-1 subtile 0: hides barrier skew
            bar_wait(mgrp, t + 1);              // h(t) fully published group-wide
            prefetchA(t + 1, 2, st0);           // chunk-2 h data
            compute(st1, 1, 2);                 // chunk-1 subtile 1: hides A fetch
        }
    }
}

// ---------------- host ----------------
extern "C" void kernel_launch(void* const* d_in, const int* in_sizes, int n_in,
                              void* d_out, int out_size) {
    const float* x     = (const float*)d_in[0];
    const float* maskX = (const float*)d_in[1];
    const float* W_ih  = (const float*)d_in[2];
    const float* W_hh  = (const float*)d_in[3];
    const float* b_ih  = (const float*)d_in[4];
    const float* b_hh  = (const float*)d_in[5];
    const float* W_lin = (const float*)d_in[6];
    const float* b_lin = (const float*)d_in[7];
    float* out = (float*)d_out;

    cudaFuncSetAttribute(lstm_persist_kernel,
                         cudaFuncAttributeMaxDynamicSharedMemorySize, DSMEM_BYTES);

    zero_kernel<<<(NGHH + 255) / 256, 256>>>();
    init_out_kernel<<<(NT * NG + 255) / 256, 256>>>(b_lin, out);
    prep_bias_kernel<<<(HH + 255) / 256, 256>>>(b_ih, b_hh);
    prep_W_kernel<<<dim3((KTOT + 255) / 256, G4), 256>>>(W_ih, W_hh);
    prep_xm_kernel<<<dim3((NG * NX) / 256, NT), 256>>>(x, maskX);

    lstm_persist_kernel<<<NBLK, 256, DSMEM_BYTES>>>(W_lin, out);
}

// round 17
// speedup vs baseline: 2.0081x; 1.0383x over previous
#include <cuda_runtime.h>
#include <cuda_fp16.h>
#include <stdint.h>
#include <math.h>

#define NT 365
#define NG 512
#define NX 256
#define HH 1024
#define KTOT 1280
#define G4 4096
#define NGHH (NG * HH)
#define NCHUNK 20                    // K=64 chunks: 0-3 = xm (K 256), 4-19 = h (K 1024)
#define STAGE_BYTES 24576            // A(8KB: 64rows x 128B) + B(16KB: 128rows x 128B)
#define SMEM_ST_OFF (2 * STAGE_BYTES)
#define DSMEM_BYTES (SMEM_ST_OFF + 64 * 132 * 4)    // 2 stages + sT = 81KB
#define NBLK 256                     // 8 m-groups x 32 col-groups; 2 CTAs/SM
#define NTHREADS 128
#define GRPSZ 32                     // CTAs per m-group barrier

// ---------------- scratch (__device__ globals; no allocation) ----------------
__device__ __half g_h[2][NGHH];                     // ping-pong, fp16
__device__ __half g_Wp[(size_t)G4 * KTOT];          // rows permuted: r' = col*4 + gate
__device__ __half g_xm[(size_t)NT * NG * NX];       // fp16
__device__ float4 g_biasp[HH];                      // per col: (bi, bf, bg, bo)
__device__ unsigned int g_bar_cnt[8 * 32];          // per m-group, padded
__device__ volatile unsigned int g_bar_gen[8 * 32];

// ---------------- PTX helpers ----------------
static __device__ __forceinline__ uint32_t smem_u32(const void* p) {
    uint32_t a;
    asm("{ .reg .u64 t; cvta.to.shared.u64 t, %1; cvt.u32.u64 %0, t; }" : "=r"(a) : "l"(p));
    return a;
}
#define SWZ(o) ((o) ^ (((o) >> 3) & 0x70))

static __device__ __forceinline__ void cp16(uint32_t dst, const void* src) {
    asm volatile("cp.async.cg.shared.global [%0], [%1], 16;" :: "r"(dst), "l"(src));
}
static __device__ __forceinline__ void cp_commit() {
    asm volatile("cp.async.commit_group;" ::: "memory");
}
template <int N>
static __device__ __forceinline__ void cp_wait() {
    asm volatile("cp.async.wait_group %0;" :: "n"(N) : "memory");
}
static __device__ __forceinline__ void ldm4(uint32_t* r, uint32_t addr) {
    asm volatile("ldmatrix.sync.aligned.m8n8.x4.shared.b16 {%0,%1,%2,%3}, [%4];"
                 : "=r"(r[0]), "=r"(r[1]), "=r"(r[2]), "=r"(r[3]) : "r"(addr));
}
static __device__ __forceinline__ void mma_f16(float* d, const uint32_t* a,
                                               uint32_t b0, uint32_t b1) {
    asm volatile(
        "mma.sync.aligned.m16n8k16.row.col.f32.f16.f16.f32 "
        "{%0,%1,%2,%3}, {%4,%5,%6,%7}, {%8,%9}, {%0,%1,%2,%3};"
        : "+f"(d[0]), "+f"(d[1]), "+f"(d[2]), "+f"(d[3])
        : "r"(a[0]), "r"(a[1]), "r"(a[2]), "r"(a[3]), "r"(b0), "r"(b1));
}
static __device__ __forceinline__ float tanh_ap(float x) {
    float y;
    asm("tanh.approx.f32 %0, %1;" : "=f"(y) : "f"(x));
    return y;
}
static __device__ __forceinline__ float sig_ap(float x) {
    return fmaf(tanh_ap(0.5f * x), 0.5f, 0.5f);
}

// per-m-group split barrier (32 CTAs each; all 256 CTAs co-resident at 2/SM)
static __device__ __forceinline__ void bar_arrive(int mgrp, int t) {
    __syncthreads();                         // whole CTA done with step t
    if (threadIdx.x == 0) {
        __threadfence();
        if (atomicAdd(&g_bar_cnt[mgrp * 32], 1u) == GRPSZ - 1) {
            g_bar_cnt[mgrp * 32] = 0;
            __threadfence();
            g_bar_gen[mgrp * 32] = (unsigned)(t + 1);
        }
    }
}
static __device__ __forceinline__ void bar_wait(int mgrp, int t) {
    if (threadIdx.x == 0) {
        while ((int)g_bar_gen[mgrp * 32] < t) { }
        __threadfence();
    }
    __syncthreads();
}

// ---------------- prep kernels ----------------
__global__ void zero_kernel() {
    int i = blockIdx.x * 256 + threadIdx.x;
    if (i < NGHH) g_h[0][i] = __float2half(0.0f);
    if (i < 8 * 32) { g_bar_cnt[i] = 0; g_bar_gen[i] = 0; }
}

__global__ void init_out_kernel(const float* __restrict__ b_lin, float* __restrict__ out) {
    int i = blockIdx.x * 256 + threadIdx.x;
    if (i < NT * NG) out[i] = b_lin[0];
}

__global__ void prep_bias_kernel(const float* __restrict__ b_ih, const float* __restrict__ b_hh) {
    int col = blockIdx.x * 256 + threadIdx.x;
    if (col >= HH) return;
    float4 v;
    v.x = b_ih[col] + b_hh[col];
    v.y = b_ih[HH + col] + b_hh[HH + col];
    v.z = b_ih[2 * HH + col] + b_hh[2 * HH + col];
    v.w = b_ih[3 * HH + col] + b_hh[3 * HH + col];
    g_biasp[col] = v;
}

// W' row r' = col*4 + gate; k cols 0..1023 from W_hh, 1024..1279 from W_ih (fused K)
__global__ void prep_W_kernel(const float* __restrict__ W_ih, const float* __restrict__ W_hh) {
    int k = blockIdx.x * 256 + threadIdx.x;
    int r = blockIdx.y;                       // old row: gate*1024 + col
    if (k >= KTOT) return;
    float v = (k < HH) ? W_hh[(size_t)r * HH + k]
                       : W_ih[(size_t)r * NX + (k - HH)];
    int gate = r >> 10, col = r & 1023;
    g_Wp[(size_t)(col * 4 + gate) * KTOT + k] = __float2half(v);
}

__global__ void prep_xm_kernel(const float* __restrict__ x, const float* __restrict__ maskX) {
    int idx = blockIdx.x * 256 + threadIdx.x;   // 0..NG*NX-1
    int t = blockIdx.y;
    size_t gi = (size_t)t * (NG * NX) + idx;
    g_xm[gi] = __float2half(x[gi] * maskX[idx]);
}

// ---------------- persistent fused LSTM: 2 CTAs/SM, M=64 tiles ----------------
// grid 256 = 8 m-groups(64 batch) x 32 col-groups(32 hidden cols x 4 gates = 128 N)
// 4 warps: mw = (w&1)*32, nw = (w>>1)*64. Serial phases of one CTA overlap the
// sibling CTA's tensor work on the same SM.
__global__ __launch_bounds__(NTHREADS, 2) void lstm_persist_kernel(
    const float* __restrict__ W_lin, float* __restrict__ out) {
    extern __shared__ char dsm[];
    const uint32_t sbase = smem_u32(dsm);
    float* sT = (float*)(dsm + SMEM_ST_OFF);    // dedicated epilogue buffer (64x132)
    const int tid = threadIdx.x;
    const int w = tid >> 5;
    const int lane = tid & 31;
    const int mgrp = blockIdx.x & 7;
    const int m0 = mgrp * 64;
    const int cgrp = blockIdx.x >> 3;
    const int n0g = cgrp * 128;

    const int prow = tid >> 3;                  // cp.async: 0..15 (+16*s)
    const int pseg = tid & 7;

    const int mw = (w & 1) * 32;                // warp m-offset (M=64)
    const int nw = (w >> 1) * 64;               // warp n-offset (N=128)
    const int lrow = lane & 15;
    const int lcol16 = (lane >> 4) * 16;

    const int tg = tid & 15;                    // epilogue col-pair group
    const int rr = tid >> 4;                    // epilogue row group (0..7)

    const int ecol = cgrp * 32 + tg * 2;
    const float4 bb0 = g_biasp[ecol];
    const float4 bb1 = g_biasp[ecol + 1];
    const float wl0 = W_lin[ecol];
    const float wl1 = W_lin[ecol + 1];

    const uint32_t st0 = sbase;
    const uint32_t st1 = sbase + STAGE_BYTES;

    float creg[8][2];                           // 8 rows x 2 cols per thread (64 rows)
#pragma unroll
    for (int p = 0; p < 8; ++p) { creg[p][0] = 0.0f; creg[p][1] = 0.0f; }

    float acc[2][8][4];

    // chunk i covers fused-K [i*64, i*64+64): i<4 -> xm, i>=4 -> h(t-1)
    auto prefetch = [&](int tt, int i, uint32_t stb) {
        const __half* aSrc;
        int astr, ak, bk;
        if (i < 4) {
            aSrc = g_xm + (size_t)tt * NG * NX; astr = NX; ak = i * 64; bk = 1024 + i * 64;
        } else {
            aSrc = g_h[tt & 1]; astr = HH; ak = (i - 4) * 64; bk = (i - 4) * 64;
        }
#pragma unroll
        for (int s = 0; s < 4; ++s) {           // A: 64 rows
            const int row = prow + s * 16;
            cp16(stb + SWZ(row * 128 + pseg * 16),
                 aSrc + (size_t)(m0 + row) * astr + ak + pseg * 8);
        }
#pragma unroll
        for (int s = 0; s < 8; ++s) {           // B: 128 rows
            const int row = prow + s * 16;
            cp16(stb + 8192 + SWZ(row * 128 + pseg * 16),
                 g_Wp + (size_t)(n0g + row) * KTOT + bk + pseg * 8);
        }
        cp_commit();
    };

    auto compute = [&](uint32_t stb) {
#pragma unroll
        for (int ks = 0; ks < 4; ++ks) {
            const int kb = ks * 32;
            uint32_t ah[2][4], bh[4][4];
#pragma unroll
            for (int im = 0; im < 2; ++im)
                ldm4(ah[im], stb + SWZ((mw + im * 16 + lrow) * 128 + kb + lcol16));
#pragma unroll
            for (int jb = 0; jb < 4; ++jb)
                ldm4(bh[jb], stb + 8192 + SWZ((nw + jb * 16 + lrow) * 128 + kb + lcol16));
#pragma unroll
            for (int im = 0; im < 2; ++im)
#pragma unroll
                for (int jn = 0; jn < 8; ++jn)
                    mma_f16(acc[im][jn], ah[im], bh[jn >> 1][jn & 1], bh[jn >> 1][(jn & 1) + 2]);
        }
    };

    auto zacc = [&]() {
#pragma unroll
        for (int im = 0; im < 2; ++im)
#pragma unroll
            for (int jn = 0; jn < 8; ++jn)
#pragma unroll
                for (int r = 0; r < 4; ++r) acc[im][jn][r] = 0.0f;
    };

    // ---- prologue: chunk 0 of step 0 ----
    prefetch(0, 0, st0);
    cp_wait<0>(); __syncthreads();
    zacc();
    prefetch(0, 1, st1);
    compute(st0);

#pragma unroll 1
    for (int t = 0; t < NT; ++t) {
        const int wbuf = (t + 1) & 1;

        // ---- mainloop: chunks 1..19 (chunk 0 computed in prior epilogue) ----
        for (int i = 1; i < NCHUNK; ++i) {
            cp_wait<0>();                       // chunk i landed
            __syncthreads();                    // visible + compute(i-1) done everywhere
            if (i + 1 < NCHUNK) {
                if (i == 3) bar_wait(mgrp, t);  // h(t-1) published before h prefetch
                prefetch(t, i + 1, ((i + 1) & 1) ? st1 : st0);
            } else if (t + 1 < NT) {
                prefetch(t + 1, 0, st0);        // next step chunk 0 (st0 free: ch18 done)
            }
            compute((i & 1) ? st1 : st0);
        }

        __syncthreads();                        // all warps done with chunk 19 (st1)

        // ---- epilogue: sT stores -> chunk-0(t+1) compute -> cell update ----
#pragma unroll
        for (int im = 0; im < 2; ++im) {
            const int r0 = mw + im * 16 + (lane >> 2);
#pragma unroll
            for (int jn = 0; jn < 8; ++jn) {
                const int nb = nw + jn * 8 + (lane & 3) * 2;
                *(float2*)&sT[r0 * 132 + nb]       = make_float2(acc[im][jn][0], acc[im][jn][1]);
                *(float2*)&sT[(r0 + 8) * 132 + nb] = make_float2(acc[im][jn][2], acc[im][jn][3]);
            }
        }
        cp_wait<0>();                           // next-step chunk 0 landed (if issued)
        __syncthreads();                        // sT + chunk-0 data visible

        if (t + 1 < NT) {
            zacc();
            prefetch(t + 1, 1, st1);            // st1 free: chunk 19 computed + synced
            compute(st0);                       // chunk 0 of t+1 (overlaps sibling CTA)
        }

        // cell update + fused output projection
#pragma unroll
        for (int p = 0; p < 8; ++p) {
            const int row = p * 8 + rr;
            const int b = m0 + row;
            const float4 gA = *(float4*)&sT[row * 132 + tg * 8];
            const float4 gB = *(float4*)&sT[row * 132 + tg * 8 + 4];

            float i0 = sig_ap(gA.x + bb0.x);
            float f0 = sig_ap(gA.y + bb0.y);
            float q0 = tanh_ap(gA.z + bb0.z);
            float o0 = sig_ap(gA.w + bb0.w);
            float i1 = sig_ap(gB.x + bb1.x);
            float f1 = sig_ap(gB.y + bb1.y);
            float q1 = tanh_ap(gB.z + bb1.z);
            float o1 = sig_ap(gB.w + bb1.w);

            float cn0 = f0 * creg[p][0] + i0 * q0;
            float cn1 = f1 * creg[p][1] + i1 * q1;
            creg[p][0] = cn0;
            creg[p][1] = cn1;
            float h0 = o0 * tanh_ap(cn0);
            float h1 = o1 * tanh_ap(cn1);

            *(__half2*)&g_h[wbuf][(size_t)b * HH + ecol] = __floats2half2_rn(h0, h1);

            float v = h0 * wl0 + h1 * wl1;
#pragma unroll
            for (int o = 8; o; o >>= 1)
                v += __shfl_xor_sync(0xFFFFFFFFu, v, o);
            if (tg == 0) atomicAdd(&out[t * NG + b], v);
        }

        bar_arrive(mgrp, t);                    // release h(t); syncs CTA (st0 consumed)
    }
}

// ---------------- host ----------------
extern "C" void kernel_launch(void* const* d_in, const int* in_sizes, int n_in,
                              void* d_out, int out_size) {
    const float* x     = (const float*)d_in[0];
    const float* maskX = (const float*)d_in[1];
    const float* W_ih  = (const float*)d_in[2];
    const float* W_hh  = (const float*)d_in[3];
    const float* b_ih  = (const float*)d_in[4];
    const float* b_hh  = (const float*)d_in[5];
    const float* W_lin = (const float*)d_in[6];
    const float* b_lin = (const float*)d_in[7];
    float* out = (float*)d_out;

    cudaFuncSetAttribute(lstm_persist_kernel,
                         cudaFuncAttributeMaxDynamicSharedMemorySize, DSMEM_BYTES);

    zero_kernel<<<(NGHH + 255) / 256, 256>>>();
    init_out_kernel<<<(NT * NG + 255) / 256, 256>>>(b_lin, out);
    prep_bias_kernel<<<(HH + 255) / 256, 256>>>(b_ih, b_hh);
    prep_W_kernel<<<dim3((KTOT + 255) / 256, G4), 256>>>(W_ih, W_hh);
    prep_xm_kernel<<<dim3((NG * NX) / 256, NT), 256>>>(x, maskX);

    lstm_persist_kernel<<<NBLK, NTHREADS, DSMEM_BYTES>>>(W_lin, out);
}